// round 1
// baseline (speedup 1.0000x reference)
#include <cuda_runtime.h>
#include <math.h>

#define EPS 1e-12f
constexpr int K      = 8;
constexpr int MAXE   = 3200000;   // 2 * E_UND
constexpr int MAXN   = 100000;
constexpr int ITERS  = 5;         // fixed by problem setup (device scalar, deterministic)

// Scratch (allocation-free rule: __device__ globals)
__device__ float g_bufA[(size_t)MAXE * K];
__device__ float g_bufB[(size_t)MAXE * K];
__device__ float g_inlog[2][(size_t)MAXN * K];
__device__ float g_pe[(size_t)MAXN * K];
__device__ float g_psi[K * K];

__device__ __forceinline__ void red_add_v4(float* p, float a, float b, float c, float d) {
    asm volatile("red.global.add.v4.f32 [%0], {%1,%2,%3,%4};"
                 :: "l"(p), "f"(a), "f"(b), "f"(c), "f"(d) : "memory");
}

__global__ void k_psi(const float* __restrict__ pot) {
    int i = threadIdx.x;
    if (i < K * K) g_psi[i] = expf(pot[i]);
}

__global__ void k_zero4(float* __restrict__ p, int n4) {
    int i = blockIdx.x * blockDim.x + threadIdx.x;
    if (i < n4) reinterpret_cast<float4*>(p)[i] = make_float4(0.f, 0.f, 0.f, 0.f);
}

// in_log[dst] += log(max(msgs, EPS))   (initial pass over the input messages)
__global__ void k_scatter(const float* __restrict__ msgs, const int* __restrict__ dst,
                          float* __restrict__ inlog, int E) {
    int e = blockIdx.x * blockDim.x + threadIdx.x;
    if (e >= E) return;
    const float4* m4 = reinterpret_cast<const float4*>(msgs + (size_t)e * K);
    float4 a = m4[0], b = m4[1];
    float l0 = __logf(fmaxf(a.x, EPS)), l1 = __logf(fmaxf(a.y, EPS));
    float l2 = __logf(fmaxf(a.z, EPS)), l3 = __logf(fmaxf(a.w, EPS));
    float l4 = __logf(fmaxf(b.x, EPS)), l5 = __logf(fmaxf(b.y, EPS));
    float l6 = __logf(fmaxf(b.z, EPS)), l7 = __logf(fmaxf(b.w, EPS));
    float* d = inlog + (size_t)dst[e] * K;
    red_add_v4(d,     l0, l1, l2, l3);
    red_add_v4(d + 4, l4, l5, l6, l7);
}

// Per-node: pe = exp(in_log_cur); also zero in_log_next for the coming scatter.
__global__ void k_pe_zero(const float* __restrict__ inlog_cur, float* __restrict__ pe,
                          float* __restrict__ inlog_next_zero, int n4) {
    int i = blockIdx.x * blockDim.x + threadIdx.x;
    if (i >= n4) return;
    float4 v = reinterpret_cast<const float4*>(inlog_cur)[i];
    float4 o;
    o.x = __expf(v.x); o.y = __expf(v.y); o.z = __expf(v.z); o.w = __expf(v.w);
    reinterpret_cast<float4*>(pe)[i] = o;
    reinterpret_cast<float4*>(inlog_next_zero)[i] = make_float4(0.f, 0.f, 0.f, 0.f);
}

// Fused message update + log-scatter for NEXT iteration's in_log.
// m_new = normalize( max(prior[src] * pe[src] / max(m_rev, EPS), EPS) @ psi )
__global__ void k_update(const float* __restrict__ cur, float* __restrict__ nxt,
                         const float* __restrict__ pe, const float* __restrict__ prior,
                         const int* __restrict__ src, const int* __restrict__ dst,
                         const int* __restrict__ rev, float* __restrict__ inlog_nxt, int E) {
    __shared__ float sp[K * K];
    if (threadIdx.x < K * K) sp[threadIdx.x] = g_psi[threadIdx.x];
    __syncthreads();

    int e = blockIdx.x * blockDim.x + threadIdx.x;
    if (e >= E) return;

    int r = rev[e];
    int s = src[e];

    const float4* mr4 = reinterpret_cast<const float4*>(cur + (size_t)r * K);
    float4 ra = mr4[0], rb = mr4[1];
    const float4* pe4 = reinterpret_cast<const float4*>(pe + (size_t)s * K);
    float4 pa = pe4[0], pb = pe4[1];
    const float4* pr4 = reinterpret_cast<const float4*>(prior + (size_t)s * K);
    float4 qa = pr4[0], qb = pr4[1];

    float t[K];
    t[0] = fmaxf(__fdividef(pa.x * qa.x, fmaxf(ra.x, EPS)), EPS);
    t[1] = fmaxf(__fdividef(pa.y * qa.y, fmaxf(ra.y, EPS)), EPS);
    t[2] = fmaxf(__fdividef(pa.z * qa.z, fmaxf(ra.z, EPS)), EPS);
    t[3] = fmaxf(__fdividef(pa.w * qa.w, fmaxf(ra.w, EPS)), EPS);
    t[4] = fmaxf(__fdividef(pb.x * qb.x, fmaxf(rb.x, EPS)), EPS);
    t[5] = fmaxf(__fdividef(pb.y * qb.y, fmaxf(rb.y, EPS)), EPS);
    t[6] = fmaxf(__fdividef(pb.z * qb.z, fmaxf(rb.z, EPS)), EPS);
    t[7] = fmaxf(__fdividef(pb.w * qb.w, fmaxf(rb.w, EPS)), EPS);

    float m[K];
#pragma unroll
    for (int k = 0; k < K; k++) m[k] = t[0] * sp[k];
#pragma unroll
    for (int j = 1; j < K; j++) {
#pragma unroll
        for (int k = 0; k < K; k++) m[k] = fmaf(t[j], sp[j * K + k], m[k]);
    }

    float ssum = (m[0] + m[1]) + (m[2] + m[3]) + ((m[4] + m[5]) + (m[6] + m[7]));
    float inv = __fdividef(1.0f, fmaxf(ssum, EPS));

    float o[K];
#pragma unroll
    for (int k = 0; k < K; k++) o[k] = m[k] * inv;

    float4* n4 = reinterpret_cast<float4*>(nxt + (size_t)e * K);
    n4[0] = make_float4(o[0], o[1], o[2], o[3]);
    n4[1] = make_float4(o[4], o[5], o[6], o[7]);

    float l[K];
#pragma unroll
    for (int k = 0; k < K; k++) l[k] = __logf(fmaxf(o[k], EPS));

    float* d = inlog_nxt + (size_t)dst[e] * K;
    red_add_v4(d,     l[0], l[1], l[2], l[3]);
    red_add_v4(d + 4, l[4], l[5], l[6], l[7]);
}

// Beliefs: out = normalize( max(prior * exp(in_log), EPS) )
__global__ void k_belief(const float* __restrict__ inlog, const float* __restrict__ prior,
                         float* __restrict__ out, int N) {
    int i = blockIdx.x * blockDim.x + threadIdx.x;
    if (i >= N) return;
    const float4* l4 = reinterpret_cast<const float4*>(inlog + (size_t)i * K);
    const float4* p4 = reinterpret_cast<const float4*>(prior + (size_t)i * K);
    float4 la = l4[0], lb = l4[1];
    float4 pa = p4[0], pb = p4[1];
    float b[K];
    b[0] = fmaxf(pa.x * __expf(la.x), EPS);
    b[1] = fmaxf(pa.y * __expf(la.y), EPS);
    b[2] = fmaxf(pa.z * __expf(la.z), EPS);
    b[3] = fmaxf(pa.w * __expf(la.w), EPS);
    b[4] = fmaxf(pb.x * __expf(lb.x), EPS);
    b[5] = fmaxf(pb.y * __expf(lb.y), EPS);
    b[6] = fmaxf(pb.z * __expf(lb.z), EPS);
    b[7] = fmaxf(pb.w * __expf(lb.w), EPS);
    float s = (b[0] + b[1]) + (b[2] + b[3]) + ((b[4] + b[5]) + (b[6] + b[7]));
    float inv = __fdividef(1.0f, fmaxf(s, EPS));
    float4* o4 = reinterpret_cast<float4*>(out + (size_t)i * K);
    o4[0] = make_float4(b[0] * inv, b[1] * inv, b[2] * inv, b[3] * inv);
    o4[1] = make_float4(b[4] * inv, b[5] * inv, b[6] * inv, b[7] * inv);
}

extern "C" void kernel_launch(void* const* d_in, const int* in_sizes, int n_in,
                              void* d_out, int out_size) {
    const float* prior     = (const float*)d_in[0];
    const float* messages  = (const float*)d_in[1];
    const float* potential = (const float*)d_in[2];
    const int*   src       = (const int*)d_in[3];
    const int*   dst       = (const int*)d_in[4];
    const int*   rev       = (const int*)d_in[5];
    // d_in[6] = iterations (device scalar); fixed at 5 by the problem setup.

    int E = in_sizes[3];
    int N = in_sizes[0] / K;
    float* out = (float*)d_out;

    float *bufA, *bufB, *inlogBase, *pe;
    cudaGetSymbolAddress((void**)&bufA, g_bufA);
    cudaGetSymbolAddress((void**)&bufB, g_bufB);
    cudaGetSymbolAddress((void**)&inlogBase, g_inlog);
    cudaGetSymbolAddress((void**)&pe, g_pe);
    float* inlog[2] = { inlogBase, inlogBase + (size_t)MAXN * K };

    const int TB = 256;
    int gE = (E + TB - 1) / TB;
    int n4 = (N * K) / 4;                  // N*K divisible by 4 (K=8)
    int gN4 = (n4 + TB - 1) / TB;
    int gN = (N + TB - 1) / TB;

    k_psi<<<1, 64>>>(potential);
    k_zero4<<<gN4, TB>>>(inlog[0], n4);
    k_scatter<<<gE, TB>>>(messages, dst, inlog[0], E);

    const float* cur = messages;
    for (int it = 0; it < ITERS; it++) {
        float* nxt = (it & 1) ? bufB : bufA;
        k_pe_zero<<<gN4, TB>>>(inlog[it & 1], pe, inlog[(it + 1) & 1], n4);
        k_update<<<gE, TB>>>(cur, nxt, pe, prior, src, dst, rev,
                             inlog[(it + 1) & 1], E);
        cur = nxt;
    }

    k_belief<<<gN, TB>>>(inlog[ITERS & 1], prior, out, N);
}

// round 2
// speedup vs baseline: 1.2248x; 1.2248x over previous
#include <cuda_runtime.h>
#include <math.h>

#define EPS 1e-12f
constexpr int K      = 8;
constexpr int MAXE   = 3200000;   // 2 * E_UND
constexpr int MAXN   = 100000;
constexpr int ITERS  = 5;         // fixed by problem setup

// Scratch (allocation-free rule: __device__ globals)
__device__ float g_msg[(size_t)MAXE * K];          // single in-place message buffer
__device__ float g_inlog[2][(size_t)MAXN * K];
__device__ float g_pp[(size_t)MAXN * K];           // prior * exp(in_log)
__device__ float g_psi[K * K];

__device__ __forceinline__ void red_add_v4(float* p, float a, float b, float c, float d) {
    asm volatile("red.global.add.v4.f32 [%0], {%1,%2,%3,%4};"
                 :: "l"(p), "f"(a), "f"(b), "f"(c), "f"(d) : "memory");
}

__global__ void k_psi(const float* __restrict__ pot) {
    int i = threadIdx.x;
    if (i < K * K) g_psi[i] = expf(pot[i]);
}

__global__ void k_zero4(float* __restrict__ p, int n4) {
    int i = blockIdx.x * blockDim.x + threadIdx.x;
    if (i < n4) reinterpret_cast<float4*>(p)[i] = make_float4(0.f, 0.f, 0.f, 0.f);
}

// Initial scatter over edge PAIRS: inlog[dst] += log(max(msgs,EPS)).
// dst[e] = src[rev[e]] (coalesced paired read), dst[rev[e]] = src[e].
__global__ void k_scatter(const float* __restrict__ msgs, const int* __restrict__ src,
                          const int* __restrict__ rev, float* __restrict__ inlog, int E2) {
    int e = blockIdx.x * blockDim.x + threadIdx.x;
    if (e >= E2) return;
    int r = rev[e];
    int s1 = src[e];
    int s2 = src[r];

    const float4* m4a = reinterpret_cast<const float4*>(msgs + (size_t)e * K);
    const float4* m4b = reinterpret_cast<const float4*>(msgs + (size_t)r * K);
    float4 a0 = m4a[0], a1 = m4a[1], b0 = m4b[0], b1 = m4b[1];

    float* d2 = inlog + (size_t)s2 * K;   // dst of edge e
    red_add_v4(d2,     __logf(fmaxf(a0.x, EPS)), __logf(fmaxf(a0.y, EPS)),
                       __logf(fmaxf(a0.z, EPS)), __logf(fmaxf(a0.w, EPS)));
    red_add_v4(d2 + 4, __logf(fmaxf(a1.x, EPS)), __logf(fmaxf(a1.y, EPS)),
                       __logf(fmaxf(a1.z, EPS)), __logf(fmaxf(a1.w, EPS)));
    float* d1 = inlog + (size_t)s1 * K;   // dst of edge r
    red_add_v4(d1,     __logf(fmaxf(b0.x, EPS)), __logf(fmaxf(b0.y, EPS)),
                       __logf(fmaxf(b0.z, EPS)), __logf(fmaxf(b0.w, EPS)));
    red_add_v4(d1 + 4, __logf(fmaxf(b1.x, EPS)), __logf(fmaxf(b1.y, EPS)),
                       __logf(fmaxf(b1.z, EPS)), __logf(fmaxf(b1.w, EPS)));
}

// Per-node: pp = prior * exp(in_log_cur); zero in_log_next.
__global__ void k_pp_zero(const float* __restrict__ inlog_cur, const float* __restrict__ prior,
                          float* __restrict__ pp, float* __restrict__ inlog_next_zero, int n4) {
    int i = blockIdx.x * blockDim.x + threadIdx.x;
    if (i >= n4) return;
    float4 v = reinterpret_cast<const float4*>(inlog_cur)[i];
    float4 p = reinterpret_cast<const float4*>(prior)[i];
    float4 o;
    o.x = p.x * __expf(v.x); o.y = p.y * __expf(v.y);
    o.z = p.z * __expf(v.z); o.w = p.w * __expf(v.w);
    reinterpret_cast<float4*>(pp)[i] = o;
    reinterpret_cast<float4*>(inlog_next_zero)[i] = make_float4(0.f, 0.f, 0.f, 0.f);
}

// Fused pair update (in-place capable) + log-scatter into next inlog.
// Thread e<E2 handles edges e and r=rev[e]:
//   m_new[e] = normalize(max(pp[s1]/max(m_old[r],EPS),EPS) @ psi)
//   m_new[r] = normalize(max(pp[s2]/max(m_old[e],EPS),EPS) @ psi)
__global__ void k_update(const float* __restrict__ cur, float* __restrict__ out,
                         const float* __restrict__ pp, const int* __restrict__ src,
                         const int* __restrict__ rev, float* __restrict__ inlog_nxt, int E2) {
    __shared__ float sp[K * K];
    if (threadIdx.x < K * K) sp[threadIdx.x] = g_psi[threadIdx.x];
    __syncthreads();

    int e = blockIdx.x * blockDim.x + threadIdx.x;
    if (e >= E2) return;

    int r  = rev[e];
    int s1 = src[e];
    int s2 = src[r];

    const float4* m4a = reinterpret_cast<const float4*>(cur + (size_t)e * K);
    const float4* m4b = reinterpret_cast<const float4*>(cur + (size_t)r * K);
    float4 ma0 = m4a[0], ma1 = m4a[1];          // old m[e]
    float4 mb0 = m4b[0], mb1 = m4b[1];          // old m[r]
    const float4* p14 = reinterpret_cast<const float4*>(pp + (size_t)s1 * K);
    const float4* p24 = reinterpret_cast<const float4*>(pp + (size_t)s2 * K);
    float4 pa0 = p14[0], pa1 = p14[1];
    float4 pb0 = p24[0], pb1 = p24[1];

    float t1[K], t2[K];
    t1[0] = fmaxf(__fdividef(pa0.x, fmaxf(mb0.x, EPS)), EPS);
    t1[1] = fmaxf(__fdividef(pa0.y, fmaxf(mb0.y, EPS)), EPS);
    t1[2] = fmaxf(__fdividef(pa0.z, fmaxf(mb0.z, EPS)), EPS);
    t1[3] = fmaxf(__fdividef(pa0.w, fmaxf(mb0.w, EPS)), EPS);
    t1[4] = fmaxf(__fdividef(pa1.x, fmaxf(mb1.x, EPS)), EPS);
    t1[5] = fmaxf(__fdividef(pa1.y, fmaxf(mb1.y, EPS)), EPS);
    t1[6] = fmaxf(__fdividef(pa1.z, fmaxf(mb1.z, EPS)), EPS);
    t1[7] = fmaxf(__fdividef(pa1.w, fmaxf(mb1.w, EPS)), EPS);

    t2[0] = fmaxf(__fdividef(pb0.x, fmaxf(ma0.x, EPS)), EPS);
    t2[1] = fmaxf(__fdividef(pb0.y, fmaxf(ma0.y, EPS)), EPS);
    t2[2] = fmaxf(__fdividef(pb0.z, fmaxf(ma0.z, EPS)), EPS);
    t2[3] = fmaxf(__fdividef(pb0.w, fmaxf(ma0.w, EPS)), EPS);
    t2[4] = fmaxf(__fdividef(pb1.x, fmaxf(ma1.x, EPS)), EPS);
    t2[5] = fmaxf(__fdividef(pb1.y, fmaxf(ma1.y, EPS)), EPS);
    t2[6] = fmaxf(__fdividef(pb1.z, fmaxf(ma1.z, EPS)), EPS);
    t2[7] = fmaxf(__fdividef(pb1.w, fmaxf(ma1.w, EPS)), EPS);

    float m1[K], m2[K];
#pragma unroll
    for (int k = 0; k < K; k++) { m1[k] = t1[0] * sp[k]; m2[k] = t2[0] * sp[k]; }
#pragma unroll
    for (int j = 1; j < K; j++) {
#pragma unroll
        for (int k = 0; k < K; k++) {
            m1[k] = fmaf(t1[j], sp[j * K + k], m1[k]);
            m2[k] = fmaf(t2[j], sp[j * K + k], m2[k]);
        }
    }

    float s1s = (m1[0] + m1[1]) + (m1[2] + m1[3]) + ((m1[4] + m1[5]) + (m1[6] + m1[7]));
    float s2s = (m2[0] + m2[1]) + (m2[2] + m2[3]) + ((m2[4] + m2[5]) + (m2[6] + m2[7]));
    float i1 = __fdividef(1.0f, fmaxf(s1s, EPS));
    float i2 = __fdividef(1.0f, fmaxf(s2s, EPS));

    float o1[K], o2[K];
#pragma unroll
    for (int k = 0; k < K; k++) { o1[k] = m1[k] * i1; o2[k] = m2[k] * i2; }

    float4* w1 = reinterpret_cast<float4*>(out + (size_t)e * K);
    float4* w2 = reinterpret_cast<float4*>(out + (size_t)r * K);
    w1[0] = make_float4(o1[0], o1[1], o1[2], o1[3]);
    w1[1] = make_float4(o1[4], o1[5], o1[6], o1[7]);
    w2[0] = make_float4(o2[0], o2[1], o2[2], o2[3]);
    w2[1] = make_float4(o2[4], o2[5], o2[6], o2[7]);

    float l1[K], l2[K];
#pragma unroll
    for (int k = 0; k < K; k++) {
        l1[k] = __logf(o1[k] > EPS ? o1[k] : EPS);
        l2[k] = __logf(o2[k] > EPS ? o2[k] : EPS);
    }

    float* d2 = inlog_nxt + (size_t)s2 * K;   // dst of edge e
    red_add_v4(d2,     l1[0], l1[1], l1[2], l1[3]);
    red_add_v4(d2 + 4, l1[4], l1[5], l1[6], l1[7]);
    float* d1 = inlog_nxt + (size_t)s1 * K;   // dst of edge r
    red_add_v4(d1,     l2[0], l2[1], l2[2], l2[3]);
    red_add_v4(d1 + 4, l2[4], l2[5], l2[6], l2[7]);
}

// Beliefs: out = normalize( max(prior * exp(in_log), EPS) )
__global__ void k_belief(const float* __restrict__ inlog, const float* __restrict__ prior,
                         float* __restrict__ out, int N) {
    int i = blockIdx.x * blockDim.x + threadIdx.x;
    if (i >= N) return;
    const float4* l4 = reinterpret_cast<const float4*>(inlog + (size_t)i * K);
    const float4* p4 = reinterpret_cast<const float4*>(prior + (size_t)i * K);
    float4 la = l4[0], lb = l4[1];
    float4 pa = p4[0], pb = p4[1];
    float b[K];
    b[0] = fmaxf(pa.x * __expf(la.x), EPS);
    b[1] = fmaxf(pa.y * __expf(la.y), EPS);
    b[2] = fmaxf(pa.z * __expf(la.z), EPS);
    b[3] = fmaxf(pa.w * __expf(la.w), EPS);
    b[4] = fmaxf(pb.x * __expf(lb.x), EPS);
    b[5] = fmaxf(pb.y * __expf(lb.y), EPS);
    b[6] = fmaxf(pb.z * __expf(lb.z), EPS);
    b[7] = fmaxf(pb.w * __expf(lb.w), EPS);
    float s = (b[0] + b[1]) + (b[2] + b[3]) + ((b[4] + b[5]) + (b[6] + b[7]));
    float inv = __fdividef(1.0f, fmaxf(s, EPS));
    float4* o4 = reinterpret_cast<float4*>(out + (size_t)i * K);
    o4[0] = make_float4(b[0] * inv, b[1] * inv, b[2] * inv, b[3] * inv);
    o4[1] = make_float4(b[4] * inv, b[5] * inv, b[6] * inv, b[7] * inv);
}

extern "C" void kernel_launch(void* const* d_in, const int* in_sizes, int n_in,
                              void* d_out, int out_size) {
    const float* prior     = (const float*)d_in[0];
    const float* messages  = (const float*)d_in[1];
    const float* potential = (const float*)d_in[2];
    const int*   src       = (const int*)d_in[3];
    // d_in[4] = dst (unused: dst[e] == src[rev[e]])
    const int*   rev       = (const int*)d_in[5];
    // d_in[6] = iterations (fixed 5 by problem setup)

    int E  = in_sizes[3];
    int E2 = E / 2;
    int N  = in_sizes[0] / K;
    float* out = (float*)d_out;

    float *msg, *inlogBase, *pp;
    cudaGetSymbolAddress((void**)&msg, g_msg);
    cudaGetSymbolAddress((void**)&inlogBase, g_inlog);
    cudaGetSymbolAddress((void**)&pp, g_pp);
    float* inlog[2] = { inlogBase, inlogBase + (size_t)MAXN * K };

    const int TB = 256;
    int gE2 = (E2 + TB - 1) / TB;
    int n4  = (N * K) / 4;
    int gN4 = (n4 + TB - 1) / TB;
    int gN  = (N + TB - 1) / TB;

    k_psi<<<1, 64>>>(potential);
    k_zero4<<<gN4, TB>>>(inlog[0], n4);
    k_scatter<<<gE2, TB>>>(messages, src, rev, inlog[0], E2);

    for (int it = 0; it < ITERS; it++) {
        k_pp_zero<<<gN4, TB>>>(inlog[it & 1], prior, pp, inlog[(it + 1) & 1], n4);
        const float* cur = (it == 0) ? messages : msg;   // iter0 reads input, writes msg;
        k_update<<<gE2, TB>>>(cur, msg, pp, src, rev,    // later iters update in place
                              inlog[(it + 1) & 1], E2);
    }

    k_belief<<<gN, TB>>>(inlog[ITERS & 1], prior, out, N);
}